// round 5
// baseline (speedup 1.0000x reference)
#include <cuda_runtime.h>
#include <math.h>
#include <stdint.h>

// Problem dims
#define BB 32    // batch
#define TT 512   // time
#define II 512   // input size
#define HH 1024  // hidden (cell) size
#define RR 512   // recurrent/projection size

#define NBLK 256 // persistent grid (co-resident: <= 148 SMs * 2 blocks)
#define NTHR 256

// ---------------------------------------------------------------------------
// Scratch (__device__ globals; no allocations anywhere)
// ---------------------------------------------------------------------------
__device__ float  g_xT[(size_t)TT * II * BB];     // [t][i][b]
__device__ float4 g_Wc0[(size_t)1024 * HH];       // [k][j] float4(i,f,g,o)
__device__ float4 g_Wc1[(size_t)1024 * HH];
__device__ float  g_WpT0[(size_t)HH * RR];        // [k][r]
__device__ float  g_WpT1[(size_t)HH * RR];
__device__ float  g_h0T[RR * BB];                 // [r][b]
__device__ float  g_h1T[RR * BB];
__device__ float  g_c0T[HH * BB];                 // [h][b]
__device__ float  g_c1T[HH * BB];
__device__ float  g_m0T[HH * BB];                 // [h][b]
__device__ float  g_m1T[HH * BB];

// ---------------------------------------------------------------------------
// Software grid barrier (sense-reversal; all NBLK blocks co-resident)
// ---------------------------------------------------------------------------
__device__ unsigned g_bar_count = 0;
__device__ volatile unsigned g_bar_gen = 0;

__device__ __forceinline__ void grid_barrier() {
    __syncthreads();
    if (threadIdx.x == 0) {
        unsigned gen = g_bar_gen;     // read BEFORE arriving (release can't happen yet)
        __threadfence();              // publish phase data + order the read above
        if (atomicAdd(&g_bar_count, 1u) == NBLK - 1u) {
            g_bar_count = 0;
            __threadfence();
            g_bar_gen = gen + 1u;     // release
        } else {
            while (g_bar_gen == gen) { __nanosleep(64); }
        }
        __threadfence();              // acquire
    }
    __syncthreads();
}

// ---------------------------------------------------------------------------
// Packed fp32x2 helpers (Blackwell fma.rn.f32x2 — 2x fp32 FMA throughput)
// ---------------------------------------------------------------------------
__device__ __forceinline__ void ffma2(unsigned long long& acc,
                                      unsigned long long a, unsigned long long b) {
    asm("fma.rn.f32x2 %0, %1, %2, %0;" : "+l"(acc) : "l"(a), "l"(b));
}
__device__ __forceinline__ unsigned long long splat2(float v) {
    unsigned long long r;
    asm("mov.b64 %0, {%1, %1};" : "=l"(r) : "f"(v));
    return r;
}

// ---------------------------------------------------------------------------
// One persistent kernel = one graph node. Does: zero state, transpose x,
// pack weights, then 513 supersteps (layer wavefront) with grid barriers.
// ---------------------------------------------------------------------------
__global__ void __launch_bounds__(NTHR, 2)
lstm_persistent(const float* __restrict__ x,
                const float* __restrict__ Wih0, const float* __restrict__ Whh0,
                const float* __restrict__ bias0, const float* __restrict__ Wp0,
                const float* __restrict__ Wih1, const float* __restrict__ Whh1,
                const float* __restrict__ bias1, const float* __restrict__ Wp1,
                float* __restrict__ out)
{
    __shared__ __align__(16) unsigned char smraw[32768];
    const int tid  = threadIdx.x;
    const int warp = tid >> 5;
    const int lane = tid & 31;
    const int blk  = blockIdx.x;

    // ---- prologue: zero recurrent state (graph is replayed; must re-zero) ----
    for (int i = blk * NTHR + tid; i < HH * BB; i += NBLK * NTHR) {
        g_c0T[i] = 0.f; g_c1T[i] = 0.f;
        if (i < RR * BB) { g_h0T[i] = 0.f; g_h1T[i] = 0.f; }
    }

    // ---- prologue: transpose x [b][t][i] -> xT[t][i][b] (8192 32x32 tiles) ----
    {
        float (*sm)[33] = (float(*)[33])smraw;
        for (int tile = blk; tile < 16 * TT; tile += NBLK) {
            const int i0 = (tile & 15) * 32;
            const int t  = tile >> 4;
            __syncthreads();
            #pragma unroll
            for (int p = 0; p < 4; ++p) {
                const int ii = tid & 31, b = (tid >> 5) + p * 8;
                sm[ii][b] = x[((size_t)b * TT + t) * II + i0 + ii];
            }
            __syncthreads();
            #pragma unroll
            for (int p = 0; p < 4; ++p) {
                const int b = tid & 31, ii = (tid >> 5) + p * 8;
                g_xT[((size_t)t * II + i0 + ii) * BB + b] = sm[ii][b];
            }
        }
    }

    // ---- prologue: pack gate weights Wc[k][j] = float4(i,f,g,o) ----
    // k<512 -> W_ih row k; k>=512 -> W_hh row k-512 (both have 512 cols here).
    {
        float (*sm)[32][33] = (float(*)[32][33])smraw;  // [4][32][33]
        for (int tile = blk; tile < 2 * 32 * 32; tile += NBLK) {
            const int layer = tile >> 10;
            const int j0 = ((tile >> 5) & 31) * 32;
            const int k0 = (tile & 31) * 32;
            const float* Wih = layer ? Wih1 : Wih0;
            const float* Whh = layer ? Whh1 : Whh0;
            float4* dst = layer ? g_Wc1 : g_Wc0;
            const float* src = (k0 < 512) ? Wih : Whh;
            const int ks0 = (k0 < 512) ? k0 : (k0 - 512);
            __syncthreads();
            #pragma unroll
            for (int it = 0; it < 16; ++it) {
                const int idx = it * NTHR + tid;
                const int kk = idx & 31, jj = (idx >> 5) & 31, g = idx >> 10;
                sm[g][jj][kk] = src[((size_t)(g * HH + j0 + jj)) * 512 + ks0 + kk];
            }
            __syncthreads();
            #pragma unroll
            for (int it = 0; it < 4; ++it) {
                const int idx = it * NTHR + tid;
                const int jj = idx & 31, kk = idx >> 5;
                dst[(size_t)(k0 + kk) * HH + j0 + jj] =
                    make_float4(sm[0][jj][kk], sm[1][jj][kk], sm[2][jj][kk], sm[3][jj][kk]);
            }
        }
    }

    // ---- prologue: pack WpT[k][r] = Wp[r][k] ----
    {
        float (*sm)[33] = (float(*)[33])smraw;
        for (int tile = blk; tile < 2 * 16 * 32; tile += NBLK) {
            const int layer = tile >> 9;
            const int r0 = ((tile >> 5) & 15) * 32;
            const int k0 = (tile & 31) * 32;
            const float* Wp = layer ? Wp1 : Wp0;
            float* dst = layer ? g_WpT1 : g_WpT0;
            __syncthreads();
            #pragma unroll
            for (int it = 0; it < 4; ++it) {
                const int idx = it * NTHR + tid;
                const int kk = idx & 31, rr = idx >> 5;
                sm[rr][kk] = Wp[(size_t)(r0 + rr) * HH + k0 + kk];
            }
            __syncthreads();
            #pragma unroll
            for (int it = 0; it < 4; ++it) {
                const int idx = it * NTHR + tid;
                const int rr = idx & 31, kk = idx >> 5;
                dst[(size_t)(k0 + kk) * RR + r0 + rr] = sm[rr][kk];
            }
        }
    }

    grid_barrier();

    // ---- unit decode (fixed per block across all supersteps) ----
    // Gates unit: (layer, j-tile of 32 hidden, batch group of 8). 256 units.
    const int g_layer = blk >> 7;
    const int g_j0 = ((blk >> 2) & 31) * 32;
    const int g_b0 = (blk & 3) * 8;
    const float4* __restrict__ g_Wc = g_layer ? g_Wc1 : g_Wc0;
    const float*  __restrict__ g_bias = g_layer ? bias1 : bias0;
    float* g_cT = g_layer ? g_c1T : g_c0T;
    float* g_mT = g_layer ? g_m1T : g_m0T;

    // Proj unit: (layer, r-tile of 32, batch group of 8). 128 units.
    const bool p_valid = blk < 128;
    const int p_layer = (blk >> 6) & 1;
    const int p_r0 = ((blk >> 2) & 15) * 32;
    const int p_b0 = (blk & 3) * 8;
    const float* __restrict__ p_mT  = p_layer ? g_m1T : g_m0T;
    const float* __restrict__ p_WpT = p_layer ? g_WpT1 : g_WpT0;
    float* p_hT = p_layer ? g_h1T : g_h0T;

    // ---- main recurrence: wavefront layer0 @ t=s, layer1 @ t=s-1 ----
    for (int s = 0; s <= TT; ++s) {
        // ===== phase 1: gates + cell update =====
        const int tg = g_layer ? (s - 1) : s;
        if ((unsigned)tg < TT) {
            const int kg = warp * 128;  // 8-warp k-split of k=1024
            const float* inp;
            if (g_layer == 0)
                inp = (kg < 512) ? (g_xT + ((size_t)tg * II + kg) * BB)
                                 : (g_h0T + (size_t)(kg - 512) * BB);
            else
                inp = (kg < 512) ? (g_h0T + (size_t)kg * BB)
                                 : (g_h1T + (size_t)(kg - 512) * BB);
            inp += g_b0;
            const float4* wp = g_Wc + (size_t)kg * HH + g_j0 + lane;

            unsigned long long acc[4][4];  // [gate][batch-pair]
            #pragma unroll
            for (int g = 0; g < 4; ++g)
                #pragma unroll
                for (int p = 0; p < 4; ++p) acc[g][p] = 0ull;

            #pragma unroll 4
            for (int k = 0; k < 128; ++k) {
                const float4 w = __ldg(wp + (size_t)k * HH);              // 32 j's coalesced
                const ulonglong2 hA = __ldg((const ulonglong2*)(inp + (size_t)k * BB));
                const ulonglong2 hB = __ldg((const ulonglong2*)(inp + (size_t)k * BB + 4));
                const unsigned long long w0 = splat2(w.x), w1 = splat2(w.y);
                const unsigned long long w2 = splat2(w.z), w3 = splat2(w.w);
                ffma2(acc[0][0], w0, hA.x); ffma2(acc[0][1], w0, hA.y);
                ffma2(acc[0][2], w0, hB.x); ffma2(acc[0][3], w0, hB.y);
                ffma2(acc[1][0], w1, hA.x); ffma2(acc[1][1], w1, hA.y);
                ffma2(acc[1][2], w1, hB.x); ffma2(acc[1][3], w1, hB.y);
                ffma2(acc[2][0], w2, hA.x); ffma2(acc[2][1], w2, hA.y);
                ffma2(acc[2][2], w2, hB.x); ffma2(acc[2][3], w2, hB.y);
                ffma2(acc[3][0], w3, hA.x); ffma2(acc[3][1], w3, hA.y);
                ffma2(acc[3][2], w3, hB.x); ffma2(acc[3][3], w3, hB.y);
            }

            unsigned long long (*smg)[32][4][4] =
                (unsigned long long(*)[32][4][4])smraw;  // [warp][j][gate][pair] 32 KB
            #pragma unroll
            for (int g = 0; g < 4; ++g)
                #pragma unroll
                for (int p = 0; p < 4; ++p)
                    smg[warp][lane][g][p] = acc[g][p];
            __syncthreads();

            // reduce across 8 warps + cell update. thread -> (j = tid>>3, b = tid&7)
            {
                const int j = tid >> 3, b = tid & 7;
                const float* sf = (const float*)smraw;
                float gv[4];
                #pragma unroll
                for (int g = 0; g < 4; ++g) {
                    float v = g_bias[g * HH + g_j0 + j];
                    #pragma unroll
                    for (int w8 = 0; w8 < 8; ++w8)
                        v += sf[(w8 * 128 + j * 4 + g) * 8 + b];
                    gv[g] = v;
                }
                const float ig = 1.f / (1.f + expf(-gv[0]));
                const float fg = 1.f / (1.f + expf(-gv[1]));
                const float gg = tanhf(gv[2]);
                const float og = 1.f / (1.f + expf(-gv[3]));
                const int ci = (g_j0 + j) * BB + g_b0 + b;
                const float c = fg * g_cT[ci] + ig * gg;
                g_cT[ci] = c;
                g_mT[ci] = og * tanhf(c);
            }
        }
        grid_barrier();

        // ===== phase 2: projection h = m @ Wp^T (+ output for layer 1) =====
        const int tp = p_layer ? (s - 1) : s;
        if (p_valid && (unsigned)tp < TT) {
            const int kg = warp * 128;
            const float* inp = p_mT + (size_t)kg * BB + p_b0;
            const float* wpp = p_WpT + (size_t)kg * RR + p_r0 + lane;

            unsigned long long acc[4] = {0ull, 0ull, 0ull, 0ull};
            #pragma unroll 4
            for (int k = 0; k < 128; ++k) {
                const float w = __ldg(wpp + (size_t)k * RR);
                const ulonglong2 hA = __ldg((const ulonglong2*)(inp + (size_t)k * BB));
                const ulonglong2 hB = __ldg((const ulonglong2*)(inp + (size_t)k * BB + 4));
                const unsigned long long ws = splat2(w);
                ffma2(acc[0], ws, hA.x); ffma2(acc[1], ws, hA.y);
                ffma2(acc[2], ws, hB.x); ffma2(acc[3], ws, hB.y);
            }
            unsigned long long (*smp)[32][4] = (unsigned long long(*)[32][4])smraw;
            #pragma unroll
            for (int p = 0; p < 4; ++p) smp[warp][lane][p] = acc[p];
            __syncthreads();

            const int r = tid & 31, b = tid >> 5;
            const float* sf = (const float*)smraw;
            float v = 0.f;
            #pragma unroll
            for (int w8 = 0; w8 < 8; ++w8)
                v += sf[(w8 * 32 + r) * 8 + b];
            p_hT[(p_r0 + r) * BB + p_b0 + b] = v;
            if (p_layer)
                out[((size_t)(p_b0 + b) * TT + tp) * RR + p_r0 + r] = v;
        }
        grid_barrier();
    }
}

// ---------------------------------------------------------------------------
// Launch: ONE kernel node (minimizes graph upload footprint; the 1029-node
// graph left a 2 MB driver upload buffer live after teardown -> rule fail).
// ---------------------------------------------------------------------------
extern "C" void kernel_launch(void* const* d_in, const int* in_sizes, int n_in,
                              void* d_out, int out_size) {
    const float* x    = (const float*)d_in[0];
    const float* Wih0 = (const float*)d_in[1];
    const float* Whh0 = (const float*)d_in[2];
    const float* b0   = (const float*)d_in[3];
    const float* Wp0  = (const float*)d_in[4];
    const float* Wih1 = (const float*)d_in[5];
    const float* Whh1 = (const float*)d_in[6];
    const float* b1   = (const float*)d_in[7];
    const float* Wp1  = (const float*)d_in[8];
    float* out = (float*)d_out;

    lstm_persistent<<<NBLK, NTHR>>>(x, Wih0, Whh0, b0, Wp0,
                                    Wih1, Whh1, b1, Wp1, out);
}

// round 7
// speedup vs baseline: 2.2777x; 2.2777x over previous
#include <cuda_runtime.h>
#include <cuda_fp16.h>
#include <math.h>
#include <stdint.h>

#define BB 32
#define TT 512
#define II 512
#define HH 1024
#define RR 512

#define NBLK 80
#define NTHR 256

// dynamic smem: A slots 16 x 4KB @0, B slots 16 x 1KB @65536  (epilogue reuses @0)
#define SMB_OFF 65536
#define DSMEM   81920

// ---------------------------------------------------------------------------
// Global scratch (device globals only; no allocations)
// ---------------------------------------------------------------------------
__device__ __align__(16) unsigned char g_WgPk[(size_t)2 * 32 * 64 * 4096]; // 16 MB gates A-frag fp16
__device__ __align__(16) unsigned char g_WpPk[(size_t)2 * 4 * 64 * 4096];  // 2 MB proj A-frag fp16
__device__ __align__(16) unsigned char g_xImg[(size_t)TT * 32768];         // 16 MB x B-frag images
__device__ __align__(16) unsigned char g_hImg[2][32768];                   // h B-frag images
__device__ __align__(16) unsigned char g_mImg[2][65536];                   // m B-frag images

__device__ unsigned g_bar_count = 0;
__device__ volatile unsigned g_bar_gen = 0;

// ---------------------------------------------------------------------------
// Helpers
// ---------------------------------------------------------------------------
__device__ __forceinline__ uint32_t smem_u32(const void* p) {
    uint32_t a;
    asm("{ .reg .u64 t; cvta.to.shared.u64 t, %1; cvt.u32.u64 %0, t; }" : "=r"(a) : "l"(p));
    return a;
}
__device__ __forceinline__ void cp16(uint32_t d, const void* s) {
    asm volatile("cp.async.cg.shared.global [%0], [%1], 16;" :: "r"(d), "l"(s) : "memory");
}
__device__ __forceinline__ void cp_commit() {
    asm volatile("cp.async.commit_group;" ::: "memory");
}
template <int N>
__device__ __forceinline__ void cp_wait() {
    asm volatile("cp.async.wait_group %0;" :: "n"(N) : "memory");
}
__device__ __forceinline__ uint4 lds128(uint32_t a) {
    uint4 v;
    asm volatile("ld.shared.v4.u32 {%0,%1,%2,%3}, [%4];"
                 : "=r"(v.x), "=r"(v.y), "=r"(v.z), "=r"(v.w) : "r"(a));
    return v;
}
__device__ __forceinline__ uint2 lds64(uint32_t a) {
    uint2 v;
    asm volatile("ld.shared.v2.u32 {%0,%1}, [%2];" : "=r"(v.x), "=r"(v.y) : "r"(a));
    return v;
}
__device__ __forceinline__ void mma16816(float* c, const uint4& a, const uint2& b) {
    asm volatile(
        "mma.sync.aligned.m16n8k16.row.col.f32.f16.f16.f32 "
        "{%0,%1,%2,%3}, {%4,%5,%6,%7}, {%8,%9}, {%0,%1,%2,%3};"
        : "+f"(c[0]), "+f"(c[1]), "+f"(c[2]), "+f"(c[3])
        : "r"(a.x), "r"(a.y), "r"(a.z), "r"(a.w), "r"(b.x), "r"(b.y));
}
__device__ __forceinline__ uint32_t pack2h(float a, float b) {
    __half2 h = __floats2half2_rn(a, b);
    return *(uint32_t*)&h;
}

__device__ __forceinline__ void grid_barrier() {
    __syncthreads();
    if (threadIdx.x == 0) {
        unsigned gen = g_bar_gen;
        __threadfence();
        if (atomicAdd(&g_bar_count, 1u) == NBLK - 1u) {
            g_bar_count = 0;
            __threadfence();
            g_bar_gen = gen + 1u;
        } else {
            while (g_bar_gen == gen) { __nanosleep(64); }
        }
        __threadfence();
    }
    __syncthreads();
}

// B-fragment-order half image address: k index kk (0..1023 via ch), batch b.
__device__ __forceinline__ uint32_t bimg_off(int k, int b) {
    const int ch = k >> 4, kk = k & 15;
    return ((uint32_t)(ch * 4 + (b >> 3)) * 32 + ((b & 7) * 4 + ((kk & 7) >> 1))) * 8
           + ((kk & 1) + 2 * (kk >> 3)) * 2;
}

// ---------------------------------------------------------------------------
// Issue one group of 8 chunks into slot parity (g&1).
// A: all 256 threads, 16B each (4KB/chunk). B: threads < bcnt, 16B each.
// ---------------------------------------------------------------------------
__device__ __forceinline__ void issue_group(int g, const unsigned char* wbase,
                                            const unsigned char* bA, const unsigned char* bB,
                                            int boff, int bcnt,
                                            uint32_t smA0, uint32_t smB0, int tid)
{
    #pragma unroll
    for (int cc = 0; cc < 8; ++cc) {
        const int c = g * 8 + cc;
        const int slot = (g & 1) * 8 + cc;
        cp16(smA0 + slot * 4096 + tid * 16, wbase + (size_t)c * 4096 + tid * 16);
        if (tid < bcnt) {
            const unsigned char* bp =
                (c < 32) ? (bA + c * 1024) : (bB + (c - 32) * 1024);
            cp16(smB0 + slot * 1024 + tid * 16, bp + boff + tid * 16);
        }
    }
    cp_commit();
}

// ---------------------------------------------------------------------------
// M=128 x N=8*NA GEMM over K=1024 (64 chunks), warp = m16 atom.
// ---------------------------------------------------------------------------
template <int NA>
__device__ __forceinline__ void gemm128(const unsigned char* wbase,
                                        const unsigned char* bA, const unsigned char* bB,
                                        int boff, int bcnt,
                                        uint32_t smA0, uint32_t smB0,
                                        float acc[NA][4], int tid, int lane)
{
    issue_group(0, wbase, bA, bB, boff, bcnt, smA0, smB0, tid);
    issue_group(1, wbase, bA, bB, boff, bcnt, smA0, smB0, tid);
    #pragma unroll 1
    for (int g = 0; g < 8; ++g) {
        if (g < 7) cp_wait<1>(); else cp_wait<0>();
        __syncthreads();
        #pragma unroll
        for (int cc = 0; cc < 8; ++cc) {
            const int slot = (g & 1) * 8 + cc;
            const uint4 A = lds128(smA0 + slot * 4096 + tid * 16);
            #pragma unroll
            for (int na = 0; na < NA; ++na) {
                const uint2 Bv = lds64(smB0 + slot * 1024 + na * 256 + lane * 8);
                mma16816(acc[na], A, Bv);
            }
        }
        __syncthreads();
        if (g < 6) issue_group(g + 2, wbase, bA, bB, boff, bcnt, smA0, smB0, tid);
    }
}

// ---------------------------------------------------------------------------
// Persistent kernel
// ---------------------------------------------------------------------------
__global__ void __launch_bounds__(NTHR)
lstm_mma(const float* __restrict__ x,
         const float* __restrict__ Wih0, const float* __restrict__ Whh0,
         const float* __restrict__ bias0, const float* __restrict__ Wp0,
         const float* __restrict__ Wih1, const float* __restrict__ Whh1,
         const float* __restrict__ bias1, const float* __restrict__ Wp1,
         float* __restrict__ out)
{
    extern __shared__ __align__(16) unsigned char smem[];
    const uint32_t smA0 = smem_u32(smem);
    const uint32_t smB0 = smA0 + SMB_OFF;
    const int tid = threadIdx.x;
    const int blk = blockIdx.x;
    const int lane = tid & 31;
    const int gtid = blk * NTHR + tid;
    const int GT = NBLK * NTHR;

    // ===== prologue: zero h images (graph replay) =====
    for (int i = gtid; i < 2 * 32768 / 16; i += GT)
        ((uint4*)g_hImg)[i] = make_uint4(0, 0, 0, 0);

    // ===== pack x -> B-fragment fp16 images [t][ch32][na][lane]*8B =====
    for (int idx = gtid; idx < 512 * 32 * 4 * 32; idx += GT) {
        const int ln = idx & 31, na = (idx >> 5) & 3, ch = (idx >> 7) & 31, t = idx >> 12;
        const int b = na * 8 + (ln >> 2);
        const int k0 = ch * 16 + (ln & 3) * 2;
        const float* sp = x + ((size_t)b * TT + t) * II + k0;
        const float2 lo = *(const float2*)sp;
        const float2 hi = *(const float2*)(sp + 8);
        uint2 o; o.x = pack2h(lo.x, lo.y); o.y = pack2h(hi.x, hi.y);
        *(uint2*)(g_xImg + ((((size_t)t * 32 + ch) * 4 + na) * 32 + ln) * 8) = o;
    }

    // ===== pack gates weights -> A-fragment order [l][mt][ch64][ma8][lane]*16B =====
    // rows unit-major/gate-minor: r_local = u*4 + g  (u = hidden unit within tile)
    for (int idx = gtid; idx < (1 << 20); idx += GT) {
        const int ln = idx & 31, ma = (idx >> 5) & 7, ch = (idx >> 8) & 63;
        const int mt = (idx >> 14) & 31, layer = idx >> 19;
        const int rl = ma * 16 + (ln >> 2);
        const int u = rl >> 2, g = rl & 3;
        const int grow = g * HH + mt * 32 + u;
        const int k0 = ch * 16 + (ln & 3) * 2;
        const float* W = (k0 < 512) ? (layer ? Wih1 : Wih0) : (layer ? Whh1 : Whh0);
        const int ks = (k0 < 512) ? k0 : (k0 - 512);
        const float* p0 = W + (size_t)grow * 512 + ks;        // rows rl and rl+8: unit u, u+2
        const float* p1 = W + (size_t)(grow + 2) * 512 + ks;
        const float2 a01 = *(const float2*)p0;
        const float2 a23 = *(const float2*)p1;
        const float2 a45 = *(const float2*)(p0 + 8);
        const float2 a67 = *(const float2*)(p1 + 8);
        uint4 o;
        o.x = pack2h(a01.x, a01.y); o.y = pack2h(a23.x, a23.y);
        o.z = pack2h(a45.x, a45.y); o.w = pack2h(a67.x, a67.y);
        *(uint4*)(g_WgPk + (((((size_t)layer * 32 + mt) * 64 + ch) * 8 + ma) * 32 + ln) * 16) = o;
    }

    // ===== pack proj weights [l][pt4][ch64][ma8][lane]*16B =====
    for (int idx = gtid; idx < (1 << 17); idx += GT) {
        const int ln = idx & 31, ma = (idx >> 5) & 7, ch = (idx >> 8) & 63;
        const int pt = (idx >> 14) & 3, layer = idx >> 16;
        const int rg = pt * 128 + ma * 16 + (ln >> 2);
        const int k0 = ch * 16 + (ln & 3) * 2;
        const float* Wp = layer ? Wp1 : Wp0;
        const float* p0 = Wp + (size_t)rg * HH + k0;
        const float* p1 = p0 + 8 * HH;
        const float2 a01 = *(const float2*)p0;
        const float2 a23 = *(const float2*)p1;
        const float2 a45 = *(const float2*)(p0 + 8);
        const float2 a67 = *(const float2*)(p1 + 8);
        uint4 o;
        o.x = pack2h(a01.x, a01.y); o.y = pack2h(a23.x, a23.y);
        o.z = pack2h(a45.x, a45.y); o.w = pack2h(a67.x, a67.y);
        *(uint4*)(g_WpPk + ((((size_t)(layer * 4 + pt) * 64 + ch) * 8 + ma) * 32 + ln) * 16) = o;
    }

    // ===== role decode =====
    const bool isGates = blk < 64;
    const int gl = blk >> 5, mt = blk & 31;               // gates
    const int q = blk - 64;
    const int pl = q >> 3, pt = (q >> 1) & 3, nh = q & 1; // proj

    float bc[4], creg[4];
    #pragma unroll
    for (int i = 0; i < 4; ++i) creg[i] = 0.f;
    if (isGates) {
        const float* bias = gl ? bias1 : bias0;
        const int u = tid >> 3;
        #pragma unroll
        for (int g = 0; g < 4; ++g) bc[g] = bias[g * HH + mt * 32 + u];
    }
    const unsigned char* wg = g_WgPk + ((size_t)(gl * 32 + mt) * 64) * 4096;
    const unsigned char* wp = g_WpPk + ((size_t)(pl * 4 + pt) * 64) * 4096;

    grid_barrier();

    // ===== main recurrence: wavefront layer0 @ t=s, layer1 @ t=s-1 =====
    for (int s = 0; s <= TT; ++s) {
        // ---- phase 1: gates GEMM + cell update ----
        if (isGates) {
            const int t = gl ? (s - 1) : s;
            if ((unsigned)t < TT) {
                const unsigned char* bA = gl ? g_hImg[0] : (g_xImg + (size_t)t * 32768);
                const unsigned char* bB = gl ? g_hImg[1] : g_hImg[0];
                float acc[4][4];
                #pragma unroll
                for (int a = 0; a < 4; ++a)
                    #pragma unroll
                    for (int b = 0; b < 4; ++b) acc[a][b] = 0.f;
                gemm128<4>(wg, bA, bB, 0, 64, smA0, smB0, acc, tid, lane);

                // exchange C frags -> [r_local][b] fp32 (stride 33)
                float* exf = (float*)smem;
                const int ma = tid >> 5;
                const int rl0 = ma * 16 + (lane >> 2);
                const int q2 = (lane & 3) * 2;
                #pragma unroll
                for (int na = 0; na < 4; ++na) {
                    exf[rl0 * 33 + na * 8 + q2]           = acc[na][0];
                    exf[rl0 * 33 + na * 8 + q2 + 1]       = acc[na][1];
                    exf[(rl0 + 8) * 33 + na * 8 + q2]     = acc[na][2];
                    exf[(rl0 + 8) * 33 + na * 8 + q2 + 1] = acc[na][3];
                }
                __syncthreads();

                const int u = tid >> 3, bq = tid & 7;
                unsigned char* mimg = g_mImg[gl];
                const int U = mt * 32 + u;
                #pragma unroll
                for (int i = 0; i < 4; ++i) {
                    const int b = bq * 4 + i;
                    const float gi = exf[(u * 4 + 0) * 33 + b] + bc[0];
                    const float gf = exf[(u * 4 + 1) * 33 + b] + bc[1];
                    const float gg = exf[(u * 4 + 2) * 33 + b] + bc[2];
                    const float go = exf[(u * 4 + 3) * 33 + b] + bc[3];
                    const float ig = 1.f / (1.f + expf(-gi));
                    const float fg = 1.f / (1.f + expf(-gf));
                    const float gv = tanhf(gg);
                    const float og = 1.f / (1.f + expf(-go));
                    const float c = fg * creg[i] + ig * gv;
                    creg[i] = c;
                    const float m = og * tanhf(c);
                    *(__half*)(mimg + bimg_off(U, b)) = __float2half_rn(m);
                }
            }
        }
        grid_barrier();

        // ---- phase 2: projection GEMM -> h images (+ output) ----
        if (!isGates) {
            const int t = pl ? (s - 1) : s;
            if ((unsigned)t < TT) {
                const unsigned char* bA = g_mImg[pl];
                const unsigned char* bB = bA + 32 * 1024;
                float acc[2][4];
                #pragma unroll
                for (int a = 0; a < 2; ++a)
                    #pragma unroll
                    for (int b = 0; b < 4; ++b) acc[a][b] = 0.f;
                gemm128<2>(wp, bA, bB, nh * 512, 32, smA0, smB0, acc, tid, lane);

                const int ma = tid >> 5;
                const int r0g = pt * 128 + ma * 16 + (lane >> 2);
                const int q2 = (lane & 3) * 2;
                unsigned char* himg = g_hImg[pl];
                #pragma unroll
                for (int nal = 0; nal < 2; ++nal) {
                    #pragma unroll
                    for (int j = 0; j < 2; ++j) {
                        const int b = (nh * 2 + nal) * 8 + q2 + j;
                        const float v0 = acc[nal][j];
                        const float v1 = acc[nal][2 + j];
                        *(__half*)(himg + bimg_off(r0g, b))     = __float2half_rn(v0);
                        *(__half*)(himg + bimg_off(r0g + 8, b)) = __float2half_rn(v1);
                        if (pl) {
                            out[((size_t)b * TT + t) * RR + r0g]     = v0;
                            out[((size_t)b * TT + t) * RR + r0g + 8] = v1;
                        }
                    }
                }
            }
        }
        grid_barrier();
    }
}

// ---------------------------------------------------------------------------
extern "C" void kernel_launch(void* const* d_in, const int* in_sizes, int n_in,
                              void* d_out, int out_size) {
    cudaFuncSetAttribute(lstm_mma, cudaFuncAttributeMaxDynamicSharedMemorySize, DSMEM);
    lstm_mma<<<NBLK, NTHR, DSMEM>>>(
        (const float*)d_in[0],
        (const float*)d_in[1], (const float*)d_in[2], (const float*)d_in[3], (const float*)d_in[4],
        (const float*)d_in[5], (const float*)d_in[6], (const float*)d_in[7], (const float*)d_in[8],
        (float*)d_out);
}

// round 9
// speedup vs baseline: 2.9608x; 1.2999x over previous
#include <cuda_runtime.h>
#include <cuda_fp16.h>
#include <math.h>
#include <stdint.h>

#define BB 32
#define TT 512
#define II 512
#define HH 1024
#define RR 512

#define NBLK 144
#define NTHR 256

// smem: A weights 128KB @0, reduce buffer (8 partial tiles, stride-33 padded) after
#define SM_A_BYTES 131072
#define RED_STRIDE 33
#define RED_TILE   (32 * RED_STRIDE)            // one [32row x 32b] partial, padded
#define RED_FLOATS (8 * RED_TILE)               // 8 warps
#define DSMEM (SM_A_BYTES + RED_FLOATS * 4)     // 131072 + 33792 = 164864

// ---------------------------------------------------------------------------
// Global scratch (device globals only; no allocations anywhere)
// ---------------------------------------------------------------------------
__device__ __align__(16) unsigned char g_WgS[(size_t)128 * 131072]; // 16 MB gates weights, smem-image order
__device__ __align__(16) unsigned char g_WpS[(size_t)16 * 131072];  // 2 MB proj weights
__device__ __align__(16) unsigned char g_xImg[(size_t)TT * 32768];  // x B-frag images per t
__device__ __align__(16) unsigned char g_hImg[2][32768];            // h B-frag images
__device__ __align__(16) unsigned char g_mImg[2][65536];            // m B-frag images

__device__ unsigned g_bar_count = 0;
__device__ volatile unsigned g_bar_gen = 0;

// ---------------------------------------------------------------------------
// Helpers
// ---------------------------------------------------------------------------
__device__ __forceinline__ uint32_t smem_u32(const void* p) {
    uint32_t a;
    asm("{ .reg .u64 t; cvta.to.shared.u64 t, %1; cvt.u32.u64 %0, t; }" : "=r"(a) : "l"(p));
    return a;
}
__device__ __forceinline__ void cp16(uint32_t d, const void* s) {
    asm volatile("cp.async.cg.shared.global [%0], [%1], 16;" :: "r"(d), "l"(s) : "memory");
}
__device__ __forceinline__ void cp_commit() { asm volatile("cp.async.commit_group;" ::: "memory"); }
template <int N>
__device__ __forceinline__ void cp_wait() { asm volatile("cp.async.wait_group %0;" :: "n"(N) : "memory"); }
__device__ __forceinline__ uint4 lds128(uint32_t a) {
    uint4 v;
    asm volatile("ld.shared.v4.u32 {%0,%1,%2,%3}, [%4];"
                 : "=r"(v.x), "=r"(v.y), "=r"(v.z), "=r"(v.w) : "r"(a));
    return v;
}
__device__ __forceinline__ uint2 ldg64(const void* p) {
    uint2 v;
    asm volatile("ld.global.nc.v2.u32 {%0,%1}, [%2];" : "=r"(v.x), "=r"(v.y) : "l"(p));
    return v;
}
__device__ __forceinline__ void mma16816(float* c, const uint4& a, const uint2& b) {
    asm volatile(
        "mma.sync.aligned.m16n8k16.row.col.f32.f16.f16.f32 "
        "{%0,%1,%2,%3}, {%4,%5,%6,%7}, {%8,%9}, {%0,%1,%2,%3};"
        : "+f"(c[0]), "+f"(c[1]), "+f"(c[2]), "+f"(c[3])
        : "r"(a.x), "r"(a.y), "r"(a.z), "r"(a.w), "r"(b.x), "r"(b.y));
}
__device__ __forceinline__ uint32_t pack2h(float a, float b) {
    __half2 h = __floats2half2_rn(a, b);
    return *(uint32_t*)&h;
}
__device__ __forceinline__ void grid_barrier() {
    __syncthreads();
    if (threadIdx.x == 0) {
        unsigned gen = g_bar_gen;
        __threadfence();
        if (atomicAdd(&g_bar_count, 1u) == NBLK - 1u) {
            g_bar_count = 0;
            __threadfence();
            g_bar_gen = gen + 1u;
        } else {
            while (g_bar_gen == gen) { __nanosleep(32); }
        }
        __threadfence();
    }
    __syncthreads();
}
// B-fragment-order half image offset for (k, batch)
__device__ __forceinline__ uint32_t bimg_off(int k, int b) {
    const int ch = k >> 4, kk = k & 15;
    return ((uint32_t)(ch * 4 + (b >> 3)) * 32 + ((b & 7) * 4 + ((kk & 7) >> 1))) * 8
           + ((kk & 1) + 2 * (kk >> 3)) * 2;
}

// ---------------------------------------------------------------------------
// One phase GEMM: D[64,32] += A(smem,128KB) x B(global frag image), K=1024.
// Warp = (m-half mh, k-quarter kq). Partials -> red[] (stride-33 padded fp32).
// Chunks 0..31 come from bA, 32..63 from bB (kq<2 -> bA, kq>=2 -> bB).
// ---------------------------------------------------------------------------
__device__ __forceinline__ void gemm_phase(uint32_t smA, float* red,
                                           const unsigned char* bA,
                                           const unsigned char* bB,
                                           int wid, int lane)
{
    const int mh = wid >> 2, kq = wid & 3;
    const unsigned char* bsrc = (kq < 2) ? bA : bB;
    const unsigned char* bp = bsrc + (size_t)((kq < 2) ? kq * 16 : kq * 16 - 32) * 1024
                              + lane * 8;
    const uint32_t abase = smA + ((kq * 16) * 4 + mh * 2) * 512 + lane * 16;

    float acc[2][4][4];
    #pragma unroll
    for (int m = 0; m < 2; ++m)
        #pragma unroll
        for (int n = 0; n < 4; ++n)
            #pragma unroll
            for (int i = 0; i < 4; ++i) acc[m][n][i] = 0.f;

    uint2 Bc[4], Bn[4];
    #pragma unroll
    for (int n = 0; n < 4; ++n) Bc[n] = ldg64(bp + n * 256);

    #pragma unroll
    for (int i = 0; i < 16; ++i) {
        if (i < 15) {
            #pragma unroll
            for (int n = 0; n < 4; ++n) Bn[n] = ldg64(bp + (i + 1) * 1024 + n * 256);
        }
        const uint4 A0 = lds128(abase + i * 2048);
        const uint4 A1 = lds128(abase + i * 2048 + 512);
        #pragma unroll
        for (int n = 0; n < 4; ++n) {
            mma16816(acc[0][n], A0, Bc[n]);
            mma16816(acc[1][n], A1, Bc[n]);
        }
        #pragma unroll
        for (int n = 0; n < 4; ++n) Bc[n] = Bn[n];
    }

    // store partial tiles: red[(mh*4+kq)] is a [32row][33] fp32 tile
    float* base = red + (mh * 4 + kq) * RED_TILE;
    const int r0 = lane >> 2;
    const int col0 = (lane & 3) * 2;
    #pragma unroll
    for (int mi = 0; mi < 2; ++mi)
        #pragma unroll
        for (int n = 0; n < 4; ++n) {
            const int row = mi * 16 + r0;
            const int col = n * 8 + col0;
            base[row * RED_STRIDE + col]           = acc[mi][n][0];
            base[row * RED_STRIDE + col + 1]       = acc[mi][n][1];
            base[(row + 8) * RED_STRIDE + col]     = acc[mi][n][2];
            base[(row + 8) * RED_STRIDE + col + 1] = acc[mi][n][3];
        }
}

// ---------------------------------------------------------------------------
// Persistent kernel
// ---------------------------------------------------------------------------
__global__ void __launch_bounds__(NTHR)
lstm_res(const float* __restrict__ x,
         const float* __restrict__ Wih0, const float* __restrict__ Whh0,
         const float* __restrict__ bias0, const float* __restrict__ Wp0,
         const float* __restrict__ Wih1, const float* __restrict__ Whh1,
         const float* __restrict__ bias1, const float* __restrict__ Wp1,
         float* __restrict__ out)
{
    extern __shared__ __align__(16) unsigned char smem[];
    const uint32_t smA = smem_u32(smem);
    float* red = (float*)(smem + SM_A_BYTES);
    const int tid = threadIdx.x;
    const int blk = blockIdx.x;
    const int wid = tid >> 5;
    const int lane = tid & 31;
    const int gtid = blk * NTHR + tid;
    const int GT = NBLK * NTHR;

    // ===== prologue: zero h images (graph replay) =====
    for (int i = gtid; i < 2 * 32768 / 16; i += GT)
        ((uint4*)g_hImg)[i] = make_uint4(0, 0, 0, 0);

    // ===== pack x -> B-frag fp16 images =====
    for (int idx = gtid; idx < 512 * 32 * 4 * 32; idx += GT) {
        const int ln = idx & 31, na = (idx >> 5) & 3, ch = (idx >> 7) & 31, t = idx >> 12;
        const int b = na * 8 + (ln >> 2);
        const int k0 = ch * 16 + (ln & 3) * 2;
        const float* sp = x + ((size_t)b * TT + t) * II + k0;
        const float2 lo = *(const float2*)sp;
        const float2 hi = *(const float2*)(sp + 8);
        uint2 o; o.x = pack2h(lo.x, lo.y); o.y = pack2h(hi.x, hi.y);
        *(uint2*)(g_xImg + ((((size_t)t * 32 + ch) * 4 + na) * 32 + ln) * 8) = o;
    }

    // ===== pack gates weights -> per-CTA smem-image order =====
    // rows unit-major/gate-minor within 64-row tile: rl = u*4 + g
    for (int idx = gtid; idx < (1 << 20); idx += GT) {
        const int ln = idx & 31, m = (idx >> 5) & 3, c = (idx >> 7) & 63;
        const int mt = (idx >> 13) & 63, layer = (idx >> 19) & 1;
        const int rl = m * 16 + (ln >> 2);
        const int u = rl >> 2, g = rl & 3;
        const int grow = g * HH + mt * 16 + u;
        const int k0 = c * 16 + (ln & 3) * 2;
        const float* W = (k0 < 512) ? (layer ? Wih1 : Wih0) : (layer ? Whh1 : Whh0);
        const int ks = (k0 < 512) ? k0 : (k0 - 512);
        const float* p0 = W + (size_t)grow * 512 + ks;       // rows rl, rl+8 = units u, u+2
        const float* p1 = W + (size_t)(grow + 2) * 512 + ks;
        const float2 a01 = *(const float2*)p0;
        const float2 a23 = *(const float2*)p1;
        const float2 a45 = *(const float2*)(p0 + 8);
        const float2 a67 = *(const float2*)(p1 + 8);
        uint4 o;
        o.x = pack2h(a01.x, a01.y); o.y = pack2h(a23.x, a23.y);
        o.z = pack2h(a45.x, a45.y); o.w = pack2h(a67.x, a67.y);
        *(uint4*)(g_WgS + (size_t)(layer * 64 + mt) * 131072 + ((c * 4 + m) * 32 + ln) * 16) = o;
    }

    // ===== pack proj weights =====
    for (int idx = gtid; idx < (1 << 17); idx += GT) {
        const int ln = idx & 31, m = (idx >> 5) & 3, c = (idx >> 7) & 63;
        const int pt = (idx >> 13) & 7, layer = (idx >> 16) & 1;
        const int rl = m * 16 + (ln >> 2);
        const int rg = pt * 64 + rl;
        const int k0 = c * 16 + (ln & 3) * 2;
        const float* Wp = layer ? Wp1 : Wp0;
        const float* p0 = Wp + (size_t)rg * HH + k0;
        const float* p1 = p0 + 8 * HH;
        const float2 a01 = *(const float2*)p0;
        const float2 a23 = *(const float2*)p1;
        const float2 a45 = *(const float2*)(p0 + 8);
        const float2 a67 = *(const float2*)(p1 + 8);
        uint4 o;
        o.x = pack2h(a01.x, a01.y); o.y = pack2h(a23.x, a23.y);
        o.z = pack2h(a45.x, a45.y); o.w = pack2h(a67.x, a67.y);
        *(uint4*)(g_WpS + (size_t)(layer * 8 + pt) * 131072 + ((c * 4 + m) * 32 + ln) * 16) = o;
    }

    grid_barrier();  // packing complete chip-wide

    // ===== role decode + resident weight load =====
    const bool isGates = blk < 128;
    const int gl = blk >> 6, mt = blk & 63;          // gates: layer, m-tile (16 units)
    const int q = blk - 128;
    const int pl = q >> 3, pt = q & 7;               // proj: layer, r-tile (64 r)

    const unsigned char* areg = isGates ? (g_WgS + (size_t)blk * 131072)
                                        : (g_WpS + (size_t)q * 131072);
    for (int i = tid; i < 8192; i += NTHR)
        cp16(smA + i * 16, areg + (size_t)i * 16);
    cp_commit(); cp_wait<0>();
    __syncthreads();

    float bc[4], creg[2];
    creg[0] = creg[1] = 0.f;
    const int eu = tid >> 4;              // gates epilogue unit (0..15)
    const int eb0 = (tid & 15) * 2;       // gates epilogue batch base
    if (isGates) {
        const float* bias = gl ? bias1 : bias0;
        #pragma unroll
        for (int g = 0; g < 4; ++g) bc[g] = bias[g * HH + mt * 16 + eu];
    }

    // ===== main recurrence: wavefront layer0 @ t=s, layer1 @ t=s-1 =====
    for (int s = 0; s <= TT; ++s) {
        // ---- phase 1: gates GEMM + cell update ----
        if (isGates) {
            const int t = gl ? (s - 1) : s;
            if ((unsigned)t < TT) {
                const unsigned char* bA = gl ? g_hImg[0] : (g_xImg + (size_t)t * 32768);
                const unsigned char* bB = gl ? g_hImg[1] : g_hImg[0];
                gemm_phase(smA, red, bA, bB, wid, lane);
                __syncthreads();

                unsigned char* mimg = g_mImg[gl];
                const int U = mt * 16 + eu;
                #pragma unroll
                for (int pp = 0; pp < 2; ++pp) {
                    const int b = eb0 + pp;
                    float gv[4];
                    #pragma unroll
                    for (int g = 0; g < 4; ++g) {
                        const int rl = eu * 4 + g;
                        const float* tb = red + (rl >> 5) * 4 * RED_TILE + (rl & 31) * RED_STRIDE + b;
                        gv[g] = bc[g] + tb[0] + tb[RED_TILE] + tb[2 * RED_TILE] + tb[3 * RED_TILE];
                    }
                    const float ig = 1.f / (1.f + expf(-gv[0]));
                    const float fg = 1.f / (1.f + expf(-gv[1]));
                    const float gg = tanhf(gv[2]);
                    const float og = 1.f / (1.f + expf(-gv[3]));
                    const float c = fg * creg[pp] + ig * gg;
                    creg[pp] = c;
                    *(__half*)(mimg + bimg_off(U, b)) = __float2half_rn(og * tanhf(c));
                }
            }
        }
        grid_barrier();

        // ---- phase 2: projection GEMM -> h image (+ final out for layer 1) ----
        if (!isGates) {
            const int t = pl ? (s - 1) : s;
            if ((unsigned)t < TT) {
                const unsigned char* bA = g_mImg[pl];
                gemm_phase(smA, red, bA, bA + 32768, wid, lane);
                __syncthreads();

                unsigned char* himg = g_hImg[pl];
                const int rl = tid >> 2;
                const int bq = (tid & 3) * 8;
                const int rg = pt * 64 + rl;
                const float* tb0 = red + (rl >> 5) * 4 * RED_TILE + (rl & 31) * RED_STRIDE;
                #pragma unroll
                for (int j = 0; j < 8; ++j) {
                    const int b = bq + j;
                    const float v = tb0[b] + tb0[RED_TILE + b]
                                  + tb0[2 * RED_TILE + b] + tb0[3 * RED_TILE + b];
                    *(__half*)(himg + bimg_off(rg, b)) = __float2half_rn(v);
                    if (pl) out[((size_t)b * TT + t) * RR + rg] = v;
                }
            }
        }
        grid_barrier();
    }
}

// ---------------------------------------------------------------------------
extern "C" void kernel_launch(void* const* d_in, const int* in_sizes, int n_in,
                              void* d_out, int out_size) {
    cudaFuncSetAttribute(lstm_res, cudaFuncAttributeMaxDynamicSharedMemorySize, DSMEM);
    lstm_res<<<NBLK, NTHR, DSMEM>>>(
        (const float*)d_in[0],
        (const float*)d_in[1], (const float*)d_in[2], (const float*)d_in[3], (const float*)d_in[4],
        (const float*)d_in[5], (const float*)d_in[6], (const float*)d_in[7], (const float*)d_in[8],
        (float*)d_out);
}

// round 10
// speedup vs baseline: 3.9708x; 1.3411x over previous
#include <cuda_runtime.h>
#include <cuda_fp16.h>
#include <math.h>
#include <stdint.h>

#define BB 32
#define TT 512
#define II 512
#define HH 1024
#define RR 512

#define NBLK 128
#define NTHR 256

// smem: gates A 128KB @0 | proj A 32KB @131072 | reduce buffer @163840
#define SM_P_OFF 131072
#define RED_OFF  163840
#define RED_STRIDE 33
#define RED_TILE   (32 * RED_STRIDE)
#define DSMEM (RED_OFF + 8 * RED_TILE * 4)   // 163840 + 33792 = 197632

// ---------------------------------------------------------------------------
// Global scratch (device globals only; no allocations anywhere)
// ---------------------------------------------------------------------------
__device__ __align__(16) unsigned char g_WgS[(size_t)128 * 131072]; // gates weights, smem-image order
__device__ __align__(16) unsigned char g_WpS[(size_t)128 * 32768];  // proj weights (8 rows/CTA, padded)
__device__ __align__(16) unsigned char g_xImg[(size_t)TT * 32768];  // x B-frag images per t
__device__ __align__(16) unsigned char g_hImg[2][32768];            // h B-frag images
__device__ __align__(16) unsigned char g_mImg[2][65536];            // m B-frag images

__device__ unsigned g_bar_count = 0;
__device__ volatile unsigned g_bar_gen = 0;

// ---------------------------------------------------------------------------
// Helpers
// ---------------------------------------------------------------------------
__device__ __forceinline__ uint32_t smem_u32(const void* p) {
    uint32_t a;
    asm("{ .reg .u64 t; cvta.to.shared.u64 t, %1; cvt.u32.u64 %0, t; }" : "=r"(a) : "l"(p));
    return a;
}
__device__ __forceinline__ void cp16(uint32_t d, const void* s) {
    asm volatile("cp.async.cg.shared.global [%0], [%1], 16;" :: "r"(d), "l"(s) : "memory");
}
__device__ __forceinline__ void cp_commit() { asm volatile("cp.async.commit_group;" ::: "memory"); }
template <int N>
__device__ __forceinline__ void cp_wait() { asm volatile("cp.async.wait_group %0;" :: "n"(N) : "memory"); }
__device__ __forceinline__ uint4 lds128(uint32_t a) {
    uint4 v;
    asm volatile("ld.shared.v4.u32 {%0,%1,%2,%3}, [%4];"
                 : "=r"(v.x), "=r"(v.y), "=r"(v.z), "=r"(v.w) : "r"(a));
    return v;
}
// L2-cached (L1-bypassing) 8B load: no L1 staleness across grid barriers.
__device__ __forceinline__ uint2 ldg64cg(const void* p) {
    uint2 v;
    asm volatile("ld.global.cg.v2.u32 {%0,%1}, [%2];" : "=r"(v.x), "=r"(v.y) : "l"(p));
    return v;
}
__device__ __forceinline__ void mma16816(float* c, const uint4& a, const uint2& b) {
    asm volatile(
        "mma.sync.aligned.m16n8k16.row.col.f32.f16.f16.f32 "
        "{%0,%1,%2,%3}, {%4,%5,%6,%7}, {%8,%9}, {%0,%1,%2,%3};"
        : "+f"(c[0]), "+f"(c[1]), "+f"(c[2]), "+f"(c[3])
        : "r"(a.x), "r"(a.y), "r"(a.z), "r"(a.w), "r"(b.x), "r"(b.y));
}
__device__ __forceinline__ uint32_t pack2h(float a, float b) {
    __half2 h = __floats2half2_rn(a, b);
    return *(uint32_t*)&h;
}
__device__ __forceinline__ void grid_barrier() {
    __syncthreads();
    if (threadIdx.x == 0) {
        unsigned gen = g_bar_gen;
        __threadfence();
        if (atomicAdd(&g_bar_count, 1u) == NBLK - 1u) {
            g_bar_count = 0;
            __threadfence();
            g_bar_gen = gen + 1u;
        } else {
            while (g_bar_gen == gen) { __nanosleep(32); }
        }
        __threadfence();
    }
    __syncthreads();
}
// B-fragment-order half image offset for (k, batch)
__device__ __forceinline__ uint32_t bimg_off(int k, int b) {
    const int ch = k >> 4, kk = k & 15;
    return ((uint32_t)(ch * 4 + (b >> 3)) * 32 + ((b & 7) * 4 + ((kk & 7) >> 1))) * 8
           + ((kk & 1) + 2 * (kk >> 3)) * 2;
}

// ---------------------------------------------------------------------------
// Gates GEMM: D[64,32] = A(smem 128KB) x B(global frag images), K=1024.
// Warp = (m-half mh, k-quarter kq); depth-4 register prefetch ring on B.
// ---------------------------------------------------------------------------
__device__ __forceinline__ void gemm_gates(uint32_t smA, float* red,
                                           const unsigned char* bA,
                                           const unsigned char* bB,
                                           int wid, int lane)
{
    const int mh = wid >> 2, kq = wid & 3;
    const unsigned char* bsrc = (kq < 2) ? bA : bB;
    const unsigned char* bp = bsrc + (size_t)((kq & 1) * 16) * 1024 + lane * 8;
    const uint32_t abase = smA + ((kq * 16) * 4 + mh * 2) * 512 + lane * 16;

    float acc[2][4][4];
    #pragma unroll
    for (int m = 0; m < 2; ++m)
        #pragma unroll
        for (int n = 0; n < 4; ++n)
            #pragma unroll
            for (int i = 0; i < 4; ++i) acc[m][n][i] = 0.f;

    uint2 ring[4][4];
    #pragma unroll
    for (int i = 0; i < 4; ++i)
        #pragma unroll
        for (int n = 0; n < 4; ++n) ring[i][n] = ldg64cg(bp + i * 1024 + n * 256);

    #pragma unroll
    for (int i = 0; i < 16; ++i) {
        const uint2 b0 = ring[i & 3][0], b1 = ring[i & 3][1];
        const uint2 b2 = ring[i & 3][2], b3 = ring[i & 3][3];
        if (i < 12) {
            #pragma unroll
            for (int n = 0; n < 4; ++n)
                ring[i & 3][n] = ldg64cg(bp + (i + 4) * 1024 + n * 256);
        }
        const uint4 A0 = lds128(abase + i * 2048);
        const uint4 A1 = lds128(abase + i * 2048 + 512);
        mma16816(acc[0][0], A0, b0); mma16816(acc[1][0], A1, b0);
        mma16816(acc[0][1], A0, b1); mma16816(acc[1][1], A1, b1);
        mma16816(acc[0][2], A0, b2); mma16816(acc[1][2], A1, b2);
        mma16816(acc[0][3], A0, b3); mma16816(acc[1][3], A1, b3);
    }

    float* base = red + (mh * 4 + kq) * RED_TILE;
    const int r0 = lane >> 2;
    const int col0 = (lane & 3) * 2;
    #pragma unroll
    for (int mi = 0; mi < 2; ++mi)
        #pragma unroll
        for (int n = 0; n < 4; ++n) {
            const int row = mi * 16 + r0;
            const int col = n * 8 + col0;
            base[row * RED_STRIDE + col]           = acc[mi][n][0];
            base[row * RED_STRIDE + col + 1]       = acc[mi][n][1];
            base[(row + 8) * RED_STRIDE + col]     = acc[mi][n][2];
            base[(row + 8) * RED_STRIDE + col + 1] = acc[mi][n][3];
        }
}

// ---------------------------------------------------------------------------
// Proj GEMM: D[8,32] = A(smem 32KB, rows 8..15 zero-padded) x m image, K=1024.
// Warp = k-eighth (8 chunks each); depth-4 ring prefetch.
// ---------------------------------------------------------------------------
__device__ __forceinline__ void gemm_proj(uint32_t smP, float* red,
                                          const unsigned char* mimg,
                                          int wid, int lane)
{
    const unsigned char* bp = mimg + (size_t)wid * 8192 + lane * 8;
    const uint32_t abase = smP + wid * 8 * 512 + lane * 16;

    float acc[4][4];
    #pragma unroll
    for (int n = 0; n < 4; ++n)
        #pragma unroll
        for (int i = 0; i < 4; ++i) acc[n][i] = 0.f;

    uint2 ring[4][4];
    #pragma unroll
    for (int i = 0; i < 4; ++i)
        #pragma unroll
        for (int n = 0; n < 4; ++n) ring[i][n] = ldg64cg(bp + i * 1024 + n * 256);

    #pragma unroll
    for (int i = 0; i < 8; ++i) {
        const uint2 b0 = ring[i & 3][0], b1 = ring[i & 3][1];
        const uint2 b2 = ring[i & 3][2], b3 = ring[i & 3][3];
        if (i < 4) {
            #pragma unroll
            for (int n = 0; n < 4; ++n)
                ring[i & 3][n] = ldg64cg(bp + (i + 4) * 1024 + n * 256);
        }
        const uint4 A = lds128(abase + i * 512);
        mma16816(acc[0], A, b0);
        mma16816(acc[1], A, b1);
        mma16816(acc[2], A, b2);
        mma16816(acc[3], A, b3);
    }

    // store only real rows 0..7 (c0,c1); rows 8..15 are the zero padding
    float* base = red + wid * RED_TILE;
    const int r0 = lane >> 2;
    const int col0 = (lane & 3) * 2;
    if (r0 < 8) {}  // all lanes' r0 in 0..7 anyway
    #pragma unroll
    for (int n = 0; n < 4; ++n) {
        base[r0 * RED_STRIDE + n * 8 + col0]     = acc[n][0];
        base[r0 * RED_STRIDE + n * 8 + col0 + 1] = acc[n][1];
    }
}

// ---------------------------------------------------------------------------
// Persistent kernel
// ---------------------------------------------------------------------------
__global__ void __launch_bounds__(NTHR)
lstm_res2(const float* __restrict__ x,
          const float* __restrict__ Wih0, const float* __restrict__ Whh0,
          const float* __restrict__ bias0, const float* __restrict__ Wp0,
          const float* __restrict__ Wih1, const float* __restrict__ Whh1,
          const float* __restrict__ bias1, const float* __restrict__ Wp1,
          float* __restrict__ out)
{
    extern __shared__ __align__(16) unsigned char smem[];
    const uint32_t smA = smem_u32(smem);
    const uint32_t smP = smA + SM_P_OFF;
    float* red = (float*)(smem + RED_OFF);
    const int tid = threadIdx.x;
    const int blk = blockIdx.x;
    const int wid = tid >> 5;
    const int lane = tid & 31;
    const int gtid = blk * NTHR + tid;
    const int GT = NBLK * NTHR;

    // ===== prologue: zero h images (graph replay) =====
    for (int i = gtid; i < 2 * 32768 / 16; i += GT)
        ((uint4*)g_hImg)[i] = make_uint4(0, 0, 0, 0);

    // ===== pack x -> B-frag fp16 images =====
    for (int idx = gtid; idx < 512 * 32 * 4 * 32; idx += GT) {
        const int ln = idx & 31, na = (idx >> 5) & 3, ch = (idx >> 7) & 31, t = idx >> 12;
        const int b = na * 8 + (ln >> 2);
        const int k0 = ch * 16 + (ln & 3) * 2;
        const float* sp = x + ((size_t)b * TT + t) * II + k0;
        const float2 lo = *(const float2*)sp;
        const float2 hi = *(const float2*)(sp + 8);
        uint2 o; o.x = pack2h(lo.x, lo.y); o.y = pack2h(hi.x, hi.y);
        *(uint2*)(g_xImg + ((((size_t)t * 32 + ch) * 4 + na) * 32 + ln) * 8) = o;
    }

    // ===== pack gates weights (rows rl = u*4 + g within 64-row tile) =====
    for (int idx = gtid; idx < (1 << 20); idx += GT) {
        const int ln = idx & 31, m = (idx >> 5) & 3, c = (idx >> 7) & 63;
        const int mt = (idx >> 13) & 63, layer = (idx >> 19) & 1;
        const int rl = m * 16 + (ln >> 2);
        const int u = rl >> 2, g = rl & 3;
        const int grow = g * HH + mt * 16 + u;
        const int k0 = c * 16 + (ln & 3) * 2;
        const float* W = (k0 < 512) ? (layer ? Wih1 : Wih0) : (layer ? Whh1 : Whh0);
        const int ks = (k0 < 512) ? k0 : (k0 - 512);
        const float* p0 = W + (size_t)grow * 512 + ks;
        const float* p1 = W + (size_t)(grow + 2) * 512 + ks;
        const float2 a01 = *(const float2*)p0;
        const float2 a23 = *(const float2*)p1;
        const float2 a45 = *(const float2*)(p0 + 8);
        const float2 a67 = *(const float2*)(p1 + 8);
        uint4 o;
        o.x = pack2h(a01.x, a01.y); o.y = pack2h(a23.x, a23.y);
        o.z = pack2h(a45.x, a45.y); o.w = pack2h(a67.x, a67.y);
        *(uint4*)(g_WgS + (size_t)(layer * 64 + mt) * 131072 + ((c * 4 + m) * 32 + ln) * 16) = o;
    }

    // ===== pack proj weights: CTA q -> rows q*8..q*8+7 (m16 rows 8..15 zero) =====
    for (int idx = gtid; idx < (1 << 18); idx += GT) {
        const int ln = idx & 31, c = (idx >> 5) & 63, q = idx >> 11;
        const int rl = ln >> 2;                 // 0..7
        const int layer = q >> 6;
        const int r = (q & 63) * 8 + rl;
        const int k0 = c * 16 + (ln & 3) * 2;
        const float* Wp = layer ? Wp1 : Wp0;
        const float* p0 = Wp + (size_t)r * HH + k0;
        uint4 o;
        o.x = pack2h(p0[0], p0[1]);
        o.y = 0u;                               // row rl+8: zero pad
        o.z = pack2h(p0[8], p0[9]);
        o.w = 0u;
        *(uint4*)(g_WpS + (size_t)q * 32768 + (c * 32 + ln) * 16) = o;
    }

    grid_barrier();  // packing complete chip-wide

    // ===== resident weight load: gates 128KB + proj 32KB =====
    {
        const unsigned char* ag = g_WgS + (size_t)blk * 131072;
        const unsigned char* ap = g_WpS + (size_t)blk * 32768;
        for (int i = tid; i < 8192; i += NTHR) cp16(smA + i * 16, ag + (size_t)i * 16);
        for (int i = tid; i < 2048; i += NTHR) cp16(smP + i * 16, ap + (size_t)i * 16);
        cp_commit(); cp_wait<0>();
        __syncthreads();
    }

    const int gl = blk >> 6, mt = blk & 63;   // gates: layer, m-tile (16 units)
    const int pl = blk >> 6;                  // proj: layer
    const int pr0 = (blk & 63) * 8;           // proj row base

    float bc[4], creg[2];
    creg[0] = creg[1] = 0.f;
    const int eu = tid >> 4;                  // gates epilogue unit (0..15)
    const int eb0 = (tid & 15) * 2;           // gates epilogue batch base
    {
        const float* bias = gl ? bias1 : bias0;
        #pragma unroll
        for (int g = 0; g < 4; ++g) bc[g] = bias[g * HH + mt * 16 + eu];
    }

    // ===== main recurrence: wavefront layer0 @ t=s, layer1 @ t=s-1 =====
    for (int s = 0; s <= TT; ++s) {
        // ---- phase 1: gates GEMM + cell update ----
        {
            const int t = gl ? (s - 1) : s;
            if ((unsigned)t < TT) {
                const unsigned char* bA = gl ? g_hImg[0] : (g_xImg + (size_t)t * 32768);
                const unsigned char* bB = gl ? g_hImg[1] : g_hImg[0];
                gemm_gates(smA, red, bA, bB, wid, lane);
                __syncthreads();

                unsigned char* mimg = g_mImg[gl];
                const int U = mt * 16 + eu;
                #pragma unroll
                for (int pp = 0; pp < 2; ++pp) {
                    const int b = eb0 + pp;
                    float gv[4];
                    #pragma unroll
                    for (int g = 0; g < 4; ++g) {
                        const int rl = eu * 4 + g;
                        const float* tb = red + (rl >> 5) * 4 * RED_TILE + (rl & 31) * RED_STRIDE + b;
                        gv[g] = bc[g] + tb[0] + tb[RED_TILE] + tb[2 * RED_TILE] + tb[3 * RED_TILE];
                    }
                    const float ig = 1.f / (1.f + expf(-gv[0]));
                    const float fg = 1.f / (1.f + expf(-gv[1]));
                    const float gg = tanhf(gv[2]);
                    const float og = 1.f / (1.f + expf(-gv[3]));
                    const float c = fg * creg[pp] + ig * gg;
                    creg[pp] = c;
                    *(__half*)(mimg + bimg_off(U, b)) = __float2half_rn(og * tanhf(c));
                }
            }
        }
        grid_barrier();

        // ---- phase 2: proj GEMM (all CTAs, 8 rows each) -> h image (+ out) ----
        {
            const int t = pl ? (s - 1) : s;
            if ((unsigned)t < TT) {
                gemm_proj(smP, red, g_mImg[pl], wid, lane);
                __syncthreads();

                unsigned char* himg = g_hImg[pl];
                const int r = tid >> 5;           // 0..7
                const int b = tid & 31;
                float v = 0.f;
                #pragma unroll
                for (int w8 = 0; w8 < 8; ++w8)
                    v += red[w8 * RED_TILE + r * RED_STRIDE + b];
                const int rg = pr0 + r;
                *(__half*)(himg + bimg_off(rg, b)) = __float2half_rn(v);
                if (pl) out[((size_t)b * TT + t) * RR + rg] = v;
            }
        }
        grid_barrier();
    }
}

// ---------------------------------------------------------------------------
extern "C" void kernel_launch(void* const* d_in, const int* in_sizes, int n_in,
                              void* d_out, int out_size) {
    cudaFuncSetAttribute(lstm_res2, cudaFuncAttributeMaxDynamicSharedMemorySize, DSMEM);
    lstm_res2<<<NBLK, NTHR, DSMEM>>>(
        (const float*)d_in[0],
        (const float*)d_in[1], (const float*)d_in[2], (const float*)d_in[3], (const float*)d_in[4],
        (const float*)d_in[5], (const float*)d_in[6], (const float*)d_in[7], (const float*)d_in[8],
        (float*)d_out);
}